// round 3
// baseline (speedup 1.0000x reference)
#include <cuda_runtime.h>
#include <cstdint>

#define NC      32
#define NSTEPS  32
#define DDIM    30
#define BLOCK   256
#define PPT     4
#define MBINS   16384          // bins per theta (2^14)
#define BPB     256            // bins per setup block
#define NT_MAX  8
#define SEQW    6              // 6 words x 6 steps x 5 bits = 36 >= 32 steps

// Per-(theta,bin) composed affine map; x-component NaN => impure bin.
__device__ float2 g_binAB[NT_MAX * MBINS];

// Compute the 32 per-cell step transforms (T00 = e^{a dT}, T01 = b*phi*...)
// for theta t into s0/s1. Call with tid in [0, BLOCK); uses tid < NC lanes.
__device__ __forceinline__ void build_table(const float* __restrict__ theta,
                                            const float* __restrict__ basis,
                                            int t, int tid,
                                            float* s0, float* s1)
{
    if (tid < NC) {
        const float dT = 1.0f / (float)NSTEPS;
        const float* __restrict__ ba = basis + (2 * tid)     * DDIM;
        const float* __restrict__ bb = basis + (2 * tid + 1) * DDIM;
        const float* __restrict__ th = theta + t * DDIM;
        float a = 0.0f, b = 0.0f;
        #pragma unroll
        for (int j = 0; j < DDIM; ++j) {
            float tj = th[j];
            a = fmaf(ba[j], tj, a);
            b = fmaf(bb[j], tj, b);
        }
        a *= dT;
        b *= dT;
        float ea  = expf(a);
        float phi = (fabsf(a) < 1e-6f) ? (1.0f + 0.5f * a) : (expm1f(a) / a);
        s0[tid] = ea;
        s1[tid] = b * phi;
    }
}

// One reference-equivalent step (also used for bin-edge trajectories).
__device__ __forceinline__ int step_cell(float x)
{
    float xc = fminf(fmaxf(x * (float)NC, 0.0f), (float)(NC - 1));
    return (int)xc;   // xc >= 0 -> trunc == floor
}

// ---------------------------------------------------------------------------
// Kernel 1: per (theta, 256-bin chunk) — trace 257 bin-edge trajectories,
// classify bins pure/impure, emit composed (A,B) or NaN sentinel.
// ---------------------------------------------------------------------------
__global__ __launch_bounds__(BLOCK)
void setup_kernel(const float* __restrict__ theta,
                  const float* __restrict__ basis)
{
    __shared__ float    s0[NC], s1[NC];
    __shared__ float    sA[BPB + 1], sB[BPB + 1];
    __shared__ uint32_t sSeq[BPB + 1][SEQW];

    const int t   = blockIdx.y;
    const int bx  = blockIdx.x;
    const int tid = threadIdx.x;

    build_table(theta, basis, t, tid, s0, s1);
    __syncthreads();

    for (int j = tid; j <= BPB; j += BLOCK) {
        // Edge x = (bx*256 + j) / 16384 — exact in fp32.
        float x = (float)(bx * BPB + j) * (1.0f / (float)MBINS);
        float A = 1.0f, B = 0.0f;
        uint32_t sw[SEQW];
        #pragma unroll
        for (int w = 0; w < SEQW; ++w) sw[w] = 0u;

        #pragma unroll
        for (int s = 0; s < NSTEPS; ++s) {
            int c = step_cell(x);
            sw[s / 6] = (sw[s / 6] << 5) | (uint32_t)c;
            float t0 = s0[c], t1 = s1[c];
            x = fmaf(t0, x, t1);
            A = A * t0;
            B = fmaf(t0, B, t1);
        }
        sA[j] = A;
        sB[j] = B;
        #pragma unroll
        for (int w = 0; w < SEQW; ++w) sSeq[j][w] = sw[w];
    }
    __syncthreads();

    if (tid < BPB) {
        bool pure = true;
        #pragma unroll
        for (int w = 0; w < SEQW; ++w)
            pure = pure && (sSeq[tid][w] == sSeq[tid + 1][w]);
        float2 r = pure ? make_float2(sA[tid], sB[tid])
                        : make_float2(__int_as_float(0x7FC00000), 0.0f);
        g_binAB[t * MBINS + bx * BPB + tid] = r;
    }
}

// ---------------------------------------------------------------------------
// Kernel 2: per point — apply composed affine if bin is pure; compact impure
// points into shared memory and iterate them with dense warps.
// ---------------------------------------------------------------------------
__global__ __launch_bounds__(BLOCK)
void main_kernel(const float* __restrict__ points,
                 const float* __restrict__ theta,
                 const float* __restrict__ basis,
                 float* __restrict__ out,
                 int n_points)
{
    __shared__ float s0[NC], s1[NC];
    __shared__ int   s_list[BLOCK * PPT];
    __shared__ int   s_cnt;

    const int t    = blockIdx.y;
    const int tid  = threadIdx.x;
    const int lane = tid & 31;

    if (tid == 0) s_cnt = 0;
    build_table(theta, basis, t, tid, s0, s1);
    __syncthreads();

    const float2* __restrict__ bt = g_binAB + t * MBINS;
    const int base = blockIdx.x * (BLOCK * PPT) + tid;
    float* __restrict__ o = out + (size_t)t * (size_t)n_points;

    #pragma unroll
    for (int k = 0; k < PPT; ++k) {
        int  idx   = base + k * BLOCK;
        bool valid = (idx < n_points);
        float x = valid ? points[idx] : 0.0f;

        // Exact floor(x * 2^14) for x in [0,1): RZ multiply cannot cross an
        // integer downward (integers <= 2^14 are representable).
        int bin = (int)__fmul_rz(x, (float)MBINS);
        bin = min(max(bin, 0), MBINS - 1);

        float2 ab = __ldg(&bt[bin]);
        bool pure = (ab.x == ab.x);        // NaN => impure

        if (valid && pure) o[idx] = fmaf(ab.x, x, ab.y);

        bool imp = valid && !pure;
        unsigned m = __ballot_sync(0xFFFFFFFFu, imp);
        if (m) {
            int leader = __ffs(m) - 1;
            int wbase  = 0;
            if (lane == leader) wbase = atomicAdd(&s_cnt, __popc(m));
            wbase = __shfl_sync(0xFFFFFFFFu, wbase, leader);
            if (imp)
                s_list[wbase + __popc(m & ((1u << lane) - 1u))] = idx;
        }
    }
    __syncthreads();

    // Slow path: densely packed warps iterate the impure points.
    const int n_imp = s_cnt;
    for (int e = tid; e < n_imp; e += BLOCK) {
        int idx = s_list[e];
        float x = points[idx];
        #pragma unroll
        for (int s = 0; s < NSTEPS; ++s) {
            int c = step_cell(x);
            x = fmaf(s0[c], x, s1[c]);
        }
        o[idx] = x;
    }
}

extern "C" void kernel_launch(void* const* d_in, const int* in_sizes, int n_in,
                              void* d_out, int out_size)
{
    const float* points = (const float*)d_in[0];  // [1, n_points]
    const float* theta  = (const float*)d_in[1];  // [n_theta, 30]
    const float* basis  = (const float*)d_in[2];  // [64, 30]
    float* out = (float*)d_out;                   // [n_theta, 1, n_points]

    const int n_points = in_sizes[0];
    const int n_theta  = in_sizes[1] / DDIM;

    dim3 sgrid(MBINS / BPB, n_theta);
    setup_kernel<<<sgrid, BLOCK>>>(theta, basis);

    dim3 mgrid((n_points + BLOCK * PPT - 1) / (BLOCK * PPT), n_theta);
    main_kernel<<<mgrid, BLOCK>>>(points, theta, basis, out, n_points);
}